// round 1
// baseline (speedup 1.0000x reference)
#include <cuda_runtime.h>
#include <math.h>

#define BATCH 4
#define NQ    300
#define NC    80
#define NK    17
#define HH    64
#define WW    64
#define HW    4096
#define NWORDS 10            // ceil(300/32)
#define BN    (BATCH*NQ)

__device__ __constant__ float NEGV = -1000000000.0f;
#define IOU_THR   0.7f
#define SCORE_THR 0.01f

// scratch: per (b,n,k): nx, ny, maxval
__device__ float g_kpts[BATCH * NQ * NK * 3];

// ---------------------------------------------------------------------------
// Kernel 1: heatmap argmax per (b,n,k) slice. One block (256 thr) per slice.
// ---------------------------------------------------------------------------
__global__ void kp_argmax_kernel(const float* __restrict__ hm,
                                 const float* __restrict__ off) {
    const int slice = blockIdx.x;               // b*NQ*NK + n*NK + k
    const int t = threadIdx.x;                  // 0..255
    const float4* p = reinterpret_cast<const float4*>(hm) + (size_t)slice * (HW / 4);

    float best = -INFINITY;
    int bi = 0;
#pragma unroll
    for (int i = 0; i < 4; i++) {
        int vi = t + i * 256;                   // ascending element index within thread
        float4 v = p[vi];
        int base = vi * 4;
        if (v.x > best) { best = v.x; bi = base; }
        if (v.y > best) { best = v.y; bi = base + 1; }
        if (v.z > best) { best = v.z; bi = base + 2; }
        if (v.w > best) { best = v.w; bi = base + 3; }
    }
    // warp reduce (lowest index wins on ties, matching jnp.argmax)
#pragma unroll
    for (int o = 16; o > 0; o >>= 1) {
        float ov = __shfl_down_sync(0xFFFFFFFFu, best, o);
        int   oi = __shfl_down_sync(0xFFFFFFFFu, bi, o);
        if (ov > best || (ov == best && oi < bi)) { best = ov; bi = oi; }
    }
    __shared__ float swv[8];
    __shared__ int   swi[8];
    if ((t & 31) == 0) { swv[t >> 5] = best; swi[t >> 5] = bi; }
    __syncthreads();
    if (t == 0) {
#pragma unroll
        for (int w = 1; w < 8; w++) {
            float ov = swv[w]; int oi = swi[w];
            if (ov > best || (ov == best && oi < bi)) { best = ov; bi = oi; }
        }
        float offx = off[(size_t)slice * 2 + 0];
        float offy = off[(size_t)slice * 2 + 1];
        float nx = (float)(bi & 63) / 63.0f + offx;
        float ny = (float)(bi >> 6) / 63.0f + offy;
        nx = fminf(fmaxf(nx, 0.0f), 1.0f);
        ny = fminf(fmaxf(ny, 0.0f), 1.0f);
        float* o = g_kpts + (size_t)slice * 3;
        o[0] = nx; o[1] = ny; o[2] = best;
    }
}

// ---------------------------------------------------------------------------
// Kernel 2: per-batch scores/labels, abs boxes, stable sort, bitmask NMS,
// stable partition (== top_k of masked scores), gather + write all outputs.
// One block of 256 threads per batch.
// ---------------------------------------------------------------------------
__global__ void nms_kernel(const float* __restrict__ logits,
                           const float* __restrict__ boxes,
                           const float* __restrict__ sizes,
                           float* __restrict__ out) {
    const int b   = blockIdx.x;
    const int tid = threadIdx.x;
    const int T   = 256;

    __shared__ float bx1[NQ], by1[NQ], bx2[NQ], by2[NQ];
    __shared__ float score[NQ];
    __shared__ int   label[NQ];
    __shared__ float skey[NQ];
    __shared__ unsigned char validA[NQ];
    __shared__ int   order[NQ];
    __shared__ float ox1[NQ], oy1[NQ], ox2[NQ], oy2[NQ], oarea[NQ];
    __shared__ unsigned char vs[NQ], keep[NQ];
    __shared__ unsigned int mask[NQ][NWORDS];
    __shared__ int   dest[NQ];
    __shared__ float red[256];
    __shared__ float s_maxc;

    const float s0 = sizes[b * 2 + 0];
    const float s1 = sizes[b * 2 + 1];

    // --- abs boxes + score/label per query ---
    float lmax = 0.0f;
    for (int n = tid; n < NQ; n += T) {
        const float* pb = boxes + ((size_t)b * NQ + n) * 4;
        float cx = pb[0], cy = pb[1], w = pb[2], h = pb[3];
        float x1 = (cx - w / 2.0f) * s0;
        float y1 = (cy - h / 2.0f) * s1;
        float x2 = (cx + w / 2.0f) * s0;
        float y2 = (cy + h / 2.0f) * s1;
        bx1[n] = x1; by1[n] = y1; bx2[n] = x2; by2[n] = y2;
        lmax = fmaxf(lmax, fmaxf(fmaxf(fabsf(x1), fabsf(y1)),
                                 fmaxf(fabsf(x2), fabsf(y2))));
        const float* pl = logits + ((size_t)b * NQ + n) * NC;
        float bestv = pl[0];
        int   bl = 0;
        for (int c = 1; c < NC; c++) {
            float v = pl[c];
            if (v > bestv) { bestv = v; bl = c; }
        }
        float sc = 1.0f / (1.0f + expf(-bestv));
        score[n]  = sc;
        label[n]  = bl;
        bool valid = sc > SCORE_THR;
        validA[n] = valid ? 1 : 0;
        skey[n]   = valid ? sc : NEGV;
    }
    red[tid] = lmax;
    __syncthreads();
    for (int s = 128; s > 0; s >>= 1) {
        if (tid < s) red[tid] = fmaxf(red[tid], red[tid + s]);
        __syncthreads();
    }
    if (tid == 0) s_maxc = red[0] + 1.0f;
    __syncthreads();
    const float maxc = s_maxc;

    // --- stable descending rank sort (matches jnp.argsort(-s)) ---
    for (int i = tid; i < NQ; i += T) {
        float si = skey[i];
        int r = 0;
        for (int j = 0; j < NQ; j++) {
            float sj = skey[j];
            r += (sj > si) || (sj == si && j < i);
        }
        order[r] = i;
    }
    __syncthreads();

    // --- sorted, class-offset boxes (offset all 4 coords, area from offsets,
    //     exactly as the reference computes) ---
    for (int r = tid; r < NQ; r += T) {
        int i = order[r];
        float o = (float)label[i] * maxc;
        float x1 = bx1[i] + o, y1 = by1[i] + o;
        float x2 = bx2[i] + o, y2 = by2[i] + o;
        ox1[r] = x1; oy1[r] = y1; ox2[r] = x2; oy2[r] = y2;
        oarea[r] = (x2 - x1) * (y2 - y1);
        vs[r] = validA[i];
    }
    __syncthreads();

    // --- IoU suppression bitmask matrix: mask[i][w] bit jj => iou(i, w*32+jj)>thr, j>i ---
    for (int widx = tid; widx < NQ * NWORDS; widx += T) {
        int i = widx / NWORDS;
        int w = widx % NWORDS;
        float x1 = ox1[i], y1 = oy1[i], x2 = ox2[i], y2 = oy2[i], ai = oarea[i];
        unsigned int bits = 0;
        int j0 = w * 32;
        for (int jj = 0; jj < 32; jj++) {
            int j = j0 + jj;
            if (j < NQ && j > i) {
                float iw = fminf(x2, ox2[j]) - fmaxf(x1, ox1[j]);
                iw = fmaxf(iw, 0.0f);
                float ih = fminf(y2, oy2[j]) - fmaxf(y1, oy1[j]);
                ih = fmaxf(ih, 0.0f);
                float inter = iw * ih;
                float iou = inter / (ai + oarea[j] - inter + 1e-9f);
                if (iou > IOU_THR) bits |= (1u << jj);
            }
        }
        mask[i][w] = bits;
    }
    __syncthreads();

    // --- greedy pass, single thread, suppression words in registers ---
    if (tid == 0) {
        unsigned int supp[NWORDS];
#pragma unroll
        for (int w = 0; w < NWORDS; w++) supp[w] = 0;
        for (int i = 0; i < NQ; i++) {
            bool k = vs[i] && !((supp[i >> 5] >> (i & 31)) & 1u);
            keep[i] = k ? 1 : 0;
            if (k) {
#pragma unroll
                for (int w = 0; w < NWORDS; w++) supp[w] |= mask[i][w];
            }
        }
    }
    __syncthreads();

    // --- stable partition: kept (ascending r) then non-kept (ascending r).
    //     This reproduces lax.top_k on masked scores exactly. ---
    for (int r = tid; r < NQ; r += T) {
        int kb = 0, nk = 0;
        for (int j = 0; j < NQ; j++) {
            int kj = keep[j];
            nk += kj;
            kb += (j < r) ? kj : 0;
        }
        dest[r] = keep[r] ? kb : (nk + (r - kb));
    }
    __syncthreads();

    // --- write outputs: fl, fb, fs, akpts, vkeep (float32, concat order) ---
    const int base = b * NQ;
    float* fl = out;
    float* fb = out + BN;
    float* fs = out + BN * 5;
    float* ak = out + BN * 6;
    float* vk = out + BN * 6 + BN * NK * 3;

    for (int r = tid; r < NQ; r += T) {
        int m = dest[r];
        int q = order[r];
        bool kf = keep[r] != 0;
        vk[base + m] = kf ? 1.0f : 0.0f;
        fl[base + m] = kf ? (float)label[q] : -1.0f;
        fs[base + m] = kf ? score[q] : 0.0f;
        float* pb = fb + (size_t)(base + m) * 4;
        pb[0] = kf ? bx1[q] : 0.0f;
        pb[1] = kf ? by1[q] : 0.0f;
        pb[2] = kf ? bx2[q] : 0.0f;
        pb[3] = kf ? by2[q] : 0.0f;
    }

    for (int idx = tid; idx < NQ * NK; idx += T) {
        int r = idx / NK;
        int k = idx % NK;
        int m = dest[r];
        int q = order[r];
        bool kf = keep[r] != 0;
        float* o = ak + ((size_t)(base + m) * NK + k) * 3;
        if (kf) {
            const float* kp = g_kpts + ((size_t)(base + q) * NK + k) * 3;
            float nx = kp[0], ny = kp[1], mv = kp[2];
            float x1 = bx1[q], x2 = bx2[q], y1 = by1[q], y2 = by2[q];
            o[0] = x1 + nx * (x2 - x1);
            o[1] = y1 + ny * (y2 - y1);
            o[2] = mv;
        } else {
            o[0] = 0.0f; o[1] = 0.0f; o[2] = 0.0f;
        }
    }
}

// ---------------------------------------------------------------------------
extern "C" void kernel_launch(void* const* d_in, const int* in_sizes, int n_in,
                              void* d_out, int out_size) {
    const float* logits = (const float*)d_in[0];   // (4,300,80)
    const float* boxes  = (const float*)d_in[1];   // (4,300,4)
    const float* hm     = (const float*)d_in[2];   // (4,300,17,64,64)
    const float* off    = (const float*)d_in[3];   // (4,300,17,2)
    const float* sizes  = (const float*)d_in[4];   // (4,2)
    float* out = (float*)d_out;

    kp_argmax_kernel<<<BATCH * NQ * NK, 256>>>(hm, off);
    nms_kernel<<<BATCH, 256>>>(logits, boxes, sizes, out);
}

// round 2
// speedup vs baseline: 2.4469x; 2.4469x over previous
#include <cuda_runtime.h>
#include <math.h>

#define BATCH 4
#define NQ    300
#define NC    80
#define NK    17
#define HW    4096
#define NWORDS 10            // ceil(300/32)
#define NWPAD  12            // padded to uint4 multiple
#define BN    (BATCH*NQ)

#define NEGV (-1000000000.0f)
#define IOU_THR   0.7f
#define SCORE_THR 0.01f

// scratch: per (b,n,k): nx, ny, maxval
__device__ float g_kpts[BATCH * NQ * NK * 3];
// selected original index per output slot (b*NQ + m)
__device__ int   g_sel[BN];

// ---------------------------------------------------------------------------
// Fused kernel: blocks 0..3 run per-batch NMS core (independent of keypoints);
// blocks 4.. run heatmap argmax. They overlap on the chip.
// ---------------------------------------------------------------------------
__global__ void fused_kernel(const float* __restrict__ logits,
                             const float* __restrict__ boxes,
                             const float* __restrict__ sizes,
                             const float* __restrict__ hm,
                             const float* __restrict__ off,
                             float* __restrict__ out) {
    const int tid = threadIdx.x;

    if (blockIdx.x >= BATCH) {
        // ---------------- heatmap argmax: one block per (b,n,k) slice -------
        const int slice = blockIdx.x - BATCH;
        const float4* p = reinterpret_cast<const float4*>(hm) + (size_t)slice * (HW / 4);

        float best = -INFINITY;
        int bi = 0;
#pragma unroll
        for (int i = 0; i < 4; i++) {
            int vi = tid + i * 256;
            float4 v = __ldcs(&p[vi]);          // streaming: read-once data
            int base = vi * 4;
            if (v.x > best) { best = v.x; bi = base; }
            if (v.y > best) { best = v.y; bi = base + 1; }
            if (v.z > best) { best = v.z; bi = base + 2; }
            if (v.w > best) { best = v.w; bi = base + 3; }
        }
#pragma unroll
        for (int o = 16; o > 0; o >>= 1) {
            float ov = __shfl_down_sync(0xFFFFFFFFu, best, o);
            int   oi = __shfl_down_sync(0xFFFFFFFFu, bi, o);
            if (ov > best || (ov == best && oi < bi)) { best = ov; bi = oi; }
        }
        __shared__ float swv[8];
        __shared__ int   swi[8];
        if ((tid & 31) == 0) { swv[tid >> 5] = best; swi[tid >> 5] = bi; }
        __syncthreads();
        if (tid == 0) {
#pragma unroll
            for (int w = 1; w < 8; w++) {
                float ov = swv[w]; int oi = swi[w];
                if (ov > best || (ov == best && oi < bi)) { best = ov; bi = oi; }
            }
            float offx = off[(size_t)slice * 2 + 0];
            float offy = off[(size_t)slice * 2 + 1];
            float nx = (float)(bi & 63) / 63.0f + offx;
            float ny = (float)(bi >> 6) / 63.0f + offy;
            nx = fminf(fmaxf(nx, 0.0f), 1.0f);
            ny = fminf(fmaxf(ny, 0.0f), 1.0f);
            float* o = g_kpts + (size_t)slice * 3;
            o[0] = nx; o[1] = ny; o[2] = best;
        }
        return;
    }

    // ---------------- NMS core: one block per batch -------------------------
    const int b = blockIdx.x;
    const int T = 256;

    __shared__ __align__(16) float bx1[NQ], by1[NQ], bx2[NQ], by2[NQ];
    __shared__ float score[NQ];
    __shared__ int   label[NQ];
    __shared__ __align__(16) float skey[NQ];
    __shared__ unsigned char validA[NQ];
    __shared__ int   order[NQ];
    __shared__ __align__(16) float4 obox[NQ];
    __shared__ float oarea[NQ];
    __shared__ unsigned char vs[NQ];
    __shared__ __align__(16) unsigned int mask[NQ][NWPAD];
    __shared__ unsigned int keepw[NWORDS];
    __shared__ float red[256];
    __shared__ float s_maxc;

    const float s0 = sizes[b * 2 + 0];
    const float s1 = sizes[b * 2 + 1];

    // --- abs boxes + score/label per query (float4 logits) ---
    float lmax = 0.0f;
    for (int n = tid; n < NQ; n += T) {
        const float* pb = boxes + ((size_t)b * NQ + n) * 4;
        float cx = pb[0], cy = pb[1], w = pb[2], h = pb[3];
        float x1 = (cx - w / 2.0f) * s0;
        float y1 = (cy - h / 2.0f) * s1;
        float x2 = (cx + w / 2.0f) * s0;
        float y2 = (cy + h / 2.0f) * s1;
        bx1[n] = x1; by1[n] = y1; bx2[n] = x2; by2[n] = y2;
        lmax = fmaxf(lmax, fmaxf(fmaxf(fabsf(x1), fabsf(y1)),
                                 fmaxf(fabsf(x2), fabsf(y2))));
        const float4* pl4 = reinterpret_cast<const float4*>(
            logits + ((size_t)b * NQ + n) * NC);
        float bestv = -INFINITY;
        int   bl = 0;
#pragma unroll 4
        for (int c4 = 0; c4 < NC / 4; c4++) {
            float4 v = pl4[c4];
            int c = c4 * 4;
            if (v.x > bestv) { bestv = v.x; bl = c; }
            if (v.y > bestv) { bestv = v.y; bl = c + 1; }
            if (v.z > bestv) { bestv = v.z; bl = c + 2; }
            if (v.w > bestv) { bestv = v.w; bl = c + 3; }
        }
        float sc = 1.0f / (1.0f + expf(-bestv));
        score[n]  = sc;
        label[n]  = bl;
        bool valid = sc > SCORE_THR;
        validA[n] = valid ? 1 : 0;
        skey[n]   = valid ? sc : NEGV;
    }
    red[tid] = lmax;
    __syncthreads();
    for (int s = 128; s > 0; s >>= 1) {
        if (tid < s) red[tid] = fmaxf(red[tid], red[tid + s]);
        __syncthreads();
    }
    if (tid == 0) s_maxc = red[0] + 1.0f;
    __syncthreads();
    const float maxc = s_maxc;

    // --- stable descending rank sort (== jnp.argsort(-s), stable) ---
    for (int i = tid; i < NQ; i += T) {
        float si = skey[i];
        int r = 0;
        const float4* sk4 = reinterpret_cast<const float4*>(skey);
#pragma unroll 5
        for (int j4 = 0; j4 < NQ / 4; j4++) {
            float4 v = sk4[j4];
            int j = j4 * 4;
            r += (v.x > si) || (v.x == si && (j    ) < i);
            r += (v.y > si) || (v.y == si && (j + 1) < i);
            r += (v.z > si) || (v.z == si && (j + 2) < i);
            r += (v.w > si) || (v.w == si && (j + 3) < i);
        }
        order[r] = i;
    }
    __syncthreads();

    // --- sorted class-offset boxes (offset all 4 coords, area from offsets) ---
    for (int r = tid; r < NQ; r += T) {
        int i = order[r];
        float o = (float)label[i] * maxc;
        float x1 = bx1[i] + o, y1 = by1[i] + o;
        float x2 = bx2[i] + o, y2 = by2[i] + o;
        obox[r] = make_float4(x1, y1, x2, y2);
        oarea[r] = (x2 - x1) * (y2 - y1);
        vs[r] = validA[i];
    }
    __syncthreads();

    // --- IoU suppression bitmask: mask[i][w] bit jj => iou(i, w*32+jj)>thr, j>i ---
    for (int widx = tid; widx < NQ * NWPAD; widx += T) {
        int i = widx / NWPAD;
        int w = widx % NWPAD;
        unsigned int bits = 0;
        if (w < NWORDS) {
            float4 bi4 = obox[i];
            float ai = oarea[i];
            int j0 = w * 32;
            for (int jj = 0; jj < 32; jj++) {
                int j = j0 + jj;
                if (j < NQ && j > i) {
                    float4 bj = obox[j];
                    float iw = fmaxf(fminf(bi4.z, bj.z) - fmaxf(bi4.x, bj.x), 0.0f);
                    float ih = fmaxf(fminf(bi4.w, bj.w) - fmaxf(bi4.y, bj.y), 0.0f);
                    float inter = iw * ih;
                    if (inter > 0.0f) {     // inter==0 -> iou==0 -> bit 0 (exact)
                        float iou = inter / (ai + oarea[j] - inter + 1e-9f);
                        if (iou > IOU_THR) bits |= (1u << jj);
                    }
                }
            }
        }
        mask[i][w] = bits;
    }
    __syncthreads();

    // --- greedy pass, single thread, branchless, vectorized mask loads ---
    if (tid == 0) {
        unsigned int supp[NWORDS];
        unsigned int kw[NWORDS];
#pragma unroll
        for (int w = 0; w < NWORDS; w++) { supp[w] = 0; kw[w] = 0; }
        for (int i = 0; i < NQ; i++) {
            unsigned int sup_bit = (supp[i >> 5] >> (i & 31)) & 1u;
            unsigned int k = (unsigned int)vs[i] & (sup_bit ^ 1u);
            unsigned int m = 0u - k;                 // 0 or 0xFFFFFFFF
            kw[i >> 5] |= k << (i & 31);
            const uint4* row = reinterpret_cast<const uint4*>(mask[i]);
            uint4 r0 = row[0], r1 = row[1], r2 = row[2];
            supp[0] |= r0.x & m; supp[1] |= r0.y & m;
            supp[2] |= r0.z & m; supp[3] |= r0.w & m;
            supp[4] |= r1.x & m; supp[5] |= r1.y & m;
            supp[6] |= r1.z & m; supp[7] |= r1.w & m;
            supp[8] |= r2.x & m; supp[9] |= r2.y & m;
        }
#pragma unroll
        for (int w = 0; w < NWORDS; w++) keepw[w] = kw[w];
    }
    __syncthreads();

    // --- stable partition via popcount (== lax.top_k on masked scores) ---
    // --- and write fl, fb, fs, vk; stash selected index for kernel 2 ---
    const int base = b * NQ;
    float* fl = out;
    float* fb = out + BN;
    float* fs = out + BN * 5;
    float* vk = out + BN * 6 + BN * NK * 3;

    for (int r = tid; r < NQ; r += T) {
        int wq = r >> 5, bq = r & 31;
        int kb = 0, nk = 0;
#pragma unroll
        for (int w = 0; w < NWORDS; w++) {
            unsigned int kwv = keepw[w];
            nk += __popc(kwv);
            if (w < wq)  kb += __popc(kwv);
            if (w == wq) kb += __popc(kwv & ((1u << bq) - 1u));
        }
        bool kf = (keepw[wq] >> bq) & 1u;
        int m = kf ? kb : (nk + (r - kb));
        int q = order[r];
        g_sel[base + m] = q;
        vk[base + m] = kf ? 1.0f : 0.0f;
        fl[base + m] = kf ? (float)label[q] : -1.0f;
        fs[base + m] = kf ? score[q] : 0.0f;
        float* pb = fb + (size_t)(base + m) * 4;
        pb[0] = kf ? bx1[q] : 0.0f;
        pb[1] = kf ? by1[q] : 0.0f;
        pb[2] = kf ? bx2[q] : 0.0f;
        pb[3] = kf ? by2[q] : 0.0f;
    }
}

// ---------------------------------------------------------------------------
// Kernel 2: keypoint gather epilogue (needs g_kpts + NMS permutation).
// ---------------------------------------------------------------------------
__global__ void akpts_kernel(float* __restrict__ out) {
    int idx = blockIdx.x * blockDim.x + threadIdx.x;
    if (idx >= BATCH * NQ * NK) return;
    int k  = idx % NK;
    int bm = idx / NK;                 // b*NQ + m
    float* ak = out + BN * 6;
    const float* vk = out + BN * 6 + BN * NK * 3;
    const float* fb = out + BN;
    float* o = ak + (size_t)idx * 3;
    if (vk[bm] != 0.0f) {
        int b = bm / NQ;
        int q = g_sel[bm];
        const float* kp = g_kpts + ((size_t)(b * NQ + q) * NK + k) * 3;
        const float* pb = fb + (size_t)bm * 4;
        float x1 = pb[0], y1 = pb[1], x2 = pb[2], y2 = pb[3];
        o[0] = x1 + kp[0] * (x2 - x1);
        o[1] = y1 + kp[1] * (y2 - y1);
        o[2] = kp[2];
    } else {
        o[0] = 0.0f; o[1] = 0.0f; o[2] = 0.0f;
    }
}

// ---------------------------------------------------------------------------
extern "C" void kernel_launch(void* const* d_in, const int* in_sizes, int n_in,
                              void* d_out, int out_size) {
    const float* logits = (const float*)d_in[0];   // (4,300,80)
    const float* boxes  = (const float*)d_in[1];   // (4,300,4)
    const float* hm     = (const float*)d_in[2];   // (4,300,17,64,64)
    const float* off    = (const float*)d_in[3];   // (4,300,17,2)
    const float* sizes  = (const float*)d_in[4];   // (4,2)
    float* out = (float*)d_out;

    fused_kernel<<<BATCH + BATCH * NQ * NK, 256>>>(logits, boxes, sizes, hm, off, out);
    int tot = BATCH * NQ * NK;
    akpts_kernel<<<(tot + 255) / 256, 256>>>(out);
}

// round 3
// speedup vs baseline: 2.4866x; 1.0163x over previous
#include <cuda_runtime.h>
#include <math.h>

#define BATCH 4
#define NQ    300
#define NC    80
#define NK    17
#define HW    4096
#define NWORDS 10            // ceil(300/32)
#define NWPAD  12            // padded row (uint4-friendly)
#define BN    (BATCH*NQ)
#define TB    1024           // threads per block
#define NSLICES (BATCH*NQ*NK)          // 20400
#define NAMB  (NSLICES/4)              // 5100 argmax blocks (4 slices each)
#define GRID_TOTAL (BATCH + NAMB)      // 5104

#define NEGV (-1000000000.0f)
#define IOU_THR   0.7f
#define SCORE_THR 0.01f

// scratch: per (b,n,k): nx, ny, maxval
__device__ float g_kpts[NSLICES * 3];
// selected original query index per output slot (b*NQ + m)
__device__ int   g_sel[BN];
// completion counter for the in-kernel epilogue
__device__ int   g_done = 0;

// ---------------------------------------------------------------------------
// Fused kernel:
//   blocks 0..3        : per-batch NMS core (1024 threads)
//   blocks 4..5103     : heatmap argmax, 4 slices per block
//   last block to exit : keypoint-gather epilogue
// ---------------------------------------------------------------------------
__global__ void __launch_bounds__(TB)
fused_kernel(const float* __restrict__ logits,
             const float* __restrict__ boxes,
             const float* __restrict__ sizes,
             const float* __restrict__ hm,
             const float* __restrict__ off,
             float* __restrict__ out) {
    const int tid = threadIdx.x;

    if (blockIdx.x >= BATCH) {
        // ---------------- heatmap argmax: 4 slices per block ----------------
        __shared__ float swv[32];
        __shared__ int   swi[32];

        const int g      = tid >> 8;             // slice group 0..3
        const int t256   = tid & 255;
        const int slice  = (blockIdx.x - BATCH) * 4 + g;
        const float4* p  = reinterpret_cast<const float4*>(hm) + (size_t)slice * (HW / 4);

        float best = -INFINITY;
        int bi = 0;
#pragma unroll
        for (int i = 0; i < 4; i++) {
            int vi = t256 + i * 256;
            float4 v = __ldcs(&p[vi]);
            int base = vi * 4;
            if (v.x > best) { best = v.x; bi = base; }
            if (v.y > best) { best = v.y; bi = base + 1; }
            if (v.z > best) { best = v.z; bi = base + 2; }
            if (v.w > best) { best = v.w; bi = base + 3; }
        }
#pragma unroll
        for (int o = 16; o > 0; o >>= 1) {
            float ov = __shfl_down_sync(0xFFFFFFFFu, best, o);
            int   oi = __shfl_down_sync(0xFFFFFFFFu, bi, o);
            if (ov > best || (ov == best && oi < bi)) { best = ov; bi = oi; }
        }
        if ((tid & 31) == 0) { swv[tid >> 5] = best; swi[tid >> 5] = bi; }
        __syncthreads();
        if (t256 == 0) {
            int w0 = g * 8;
            best = swv[w0]; bi = swi[w0];
#pragma unroll
            for (int w = 1; w < 8; w++) {
                float ov = swv[w0 + w]; int oi = swi[w0 + w];
                if (ov > best || (ov == best && oi < bi)) { best = ov; bi = oi; }
            }
            float offx = off[(size_t)slice * 2 + 0];
            float offy = off[(size_t)slice * 2 + 1];
            float nx = (float)(bi & 63) / 63.0f + offx;
            float ny = (float)(bi >> 6) / 63.0f + offy;
            nx = fminf(fmaxf(nx, 0.0f), 1.0f);
            ny = fminf(fmaxf(ny, 0.0f), 1.0f);
            float* o = g_kpts + (size_t)slice * 3;
            o[0] = nx; o[1] = ny; o[2] = best;
        }
    } else {
        // ---------------- NMS core: one block per batch ---------------------
        const int b = blockIdx.x;

        __shared__ __align__(16) float bx1[NQ], by1[NQ], bx2[NQ], by2[NQ];
        __shared__ float score[NQ];
        __shared__ int   label[NQ];
        __shared__ __align__(16) float skey[NQ];
        __shared__ unsigned char validA[NQ];
        __shared__ int   order[NQ];
        __shared__ __align__(16) float4 obox[NQ];
        __shared__ float oarea[NQ];
        __shared__ unsigned char vs[NQ];
        __shared__ __align__(16) unsigned int mask[NQ][NWPAD];
        __shared__ unsigned int keepw[NWORDS];
        __shared__ float red[TB];
        __shared__ float s_maxc;

        const float s0 = sizes[b * 2 + 0];
        const float s1 = sizes[b * 2 + 1];

        // --- abs boxes + score/label per query (one query per thread) ---
        float lmax = 0.0f;
        if (tid < NQ) {
            int n = tid;
            const float* pb = boxes + ((size_t)b * NQ + n) * 4;
            float cx = pb[0], cy = pb[1], w = pb[2], h = pb[3];
            float x1 = (cx - w / 2.0f) * s0;
            float y1 = (cy - h / 2.0f) * s1;
            float x2 = (cx + w / 2.0f) * s0;
            float y2 = (cy + h / 2.0f) * s1;
            bx1[n] = x1; by1[n] = y1; bx2[n] = x2; by2[n] = y2;
            lmax = fmaxf(fmaxf(fabsf(x1), fabsf(y1)),
                         fmaxf(fabsf(x2), fabsf(y2)));
            const float4* pl4 = reinterpret_cast<const float4*>(
                logits + ((size_t)b * NQ + n) * NC);
            float bestv = -INFINITY;
            int   bl = 0;
#pragma unroll 4
            for (int c4 = 0; c4 < NC / 4; c4++) {
                float4 v = pl4[c4];
                int c = c4 * 4;
                if (v.x > bestv) { bestv = v.x; bl = c; }
                if (v.y > bestv) { bestv = v.y; bl = c + 1; }
                if (v.z > bestv) { bestv = v.z; bl = c + 2; }
                if (v.w > bestv) { bestv = v.w; bl = c + 3; }
            }
            float sc = 1.0f / (1.0f + expf(-bestv));
            score[n]  = sc;
            label[n]  = bl;
            bool valid = sc > SCORE_THR;
            validA[n] = valid ? 1 : 0;
            skey[n]   = valid ? sc : NEGV;
        }
        red[tid] = lmax;
        __syncthreads();
        for (int s = TB / 2; s > 0; s >>= 1) {
            if (tid < s) red[tid] = fmaxf(red[tid], red[tid + s]);
            __syncthreads();
        }
        if (tid == 0) s_maxc = red[0] + 1.0f;
        __syncthreads();
        const float maxc = s_maxc;

        // --- stable descending rank sort (== jnp.argsort(-s), stable) ---
        if (tid < NQ) {
            int i = tid;
            float si = skey[i];
            int r = 0;
            const float4* sk4 = reinterpret_cast<const float4*>(skey);
#pragma unroll 5
            for (int j4 = 0; j4 < NQ / 4; j4++) {
                float4 v = sk4[j4];
                int j = j4 * 4;
                r += (v.x > si) || (v.x == si && (j    ) < i);
                r += (v.y > si) || (v.y == si && (j + 1) < i);
                r += (v.z > si) || (v.z == si && (j + 2) < i);
                r += (v.w > si) || (v.w == si && (j + 3) < i);
            }
            order[r] = i;
        }
        __syncthreads();

        // --- sorted class-offset boxes (offset all 4 coords, area from offsets) ---
        if (tid < NQ) {
            int r = tid;
            int i = order[r];
            float o = (float)label[i] * maxc;
            float x1 = bx1[i] + o, y1 = by1[i] + o;
            float x2 = bx2[i] + o, y2 = by2[i] + o;
            obox[r] = make_float4(x1, y1, x2, y2);
            oarea[r] = (x2 - x1) * (y2 - y1);
            vs[r] = validA[i];
        }
        __syncthreads();

        // --- IoU suppression bitmask: mask[i][w] bit jj => iou(i, w*32+jj)>thr, j>i ---
        for (int widx = tid; widx < NQ * NWPAD; widx += TB) {
            int i = widx / NWPAD;
            int w = widx % NWPAD;
            unsigned int bits = 0;
            if (w < NWORDS) {
                float4 bi4 = obox[i];
                float ai = oarea[i];
                int j0 = w * 32;
                for (int jj = 0; jj < 32; jj++) {
                    int j = j0 + jj;
                    if (j < NQ && j > i) {
                        float4 bj = obox[j];
                        float iw = fmaxf(fminf(bi4.z, bj.z) - fmaxf(bi4.x, bj.x), 0.0f);
                        float ih = fmaxf(fminf(bi4.w, bj.w) - fmaxf(bi4.y, bj.y), 0.0f);
                        float inter = iw * ih;
                        if (inter > 0.0f) {   // inter==0 -> iou==0 -> bit 0 (exact)
                            float iou = inter / (ai + oarea[j] - inter + 1e-9f);
                            if (iou > IOU_THR) bits |= (1u << jj);
                        }
                    }
                }
            }
            mask[i][w] = bits;
        }
        __syncthreads();

        // --- greedy pass: warp 0, lane w owns supp word w (scalar regs) ---
        if (tid < 32) {
            const int lane = tid;
            unsigned int supp_w = 0, kw_w = 0;
            for (int i = 0; i < NQ; i++) {
                unsigned int sw = __shfl_sync(0xFFFFFFFFu, supp_w, i >> 5);
                unsigned int sup_bit = (sw >> (i & 31)) & 1u;
                unsigned int k = (unsigned int)vs[i] & (sup_bit ^ 1u);
                unsigned int m = 0u - k;                 // 0 or 0xFFFFFFFF
                if (lane == (i >> 5)) kw_w |= k << (i & 31);
                if (lane < NWORDS) supp_w |= mask[i][lane] & m;
            }
            if (lane < NWORDS) keepw[lane] = kw_w;
        }
        __syncthreads();

        // --- stable partition via popcount (== lax.top_k on masked scores) ---
        // --- and write fl, fb, fs, vk; stash selected index for epilogue ---
        const int base = b * NQ;
        float* fl = out;
        float* fb = out + BN;
        float* fs = out + BN * 5;
        float* vk = out + BN * 6 + BN * NK * 3;

        if (tid < NQ) {
            int r = tid;
            int wq = r >> 5, bq = r & 31;
            int kb = 0, nk = 0;
#pragma unroll
            for (int w = 0; w < NWORDS; w++) {
                unsigned int kwv = keepw[w];
                nk += __popc(kwv);
                if (w < wq)  kb += __popc(kwv);
                if (w == wq) kb += __popc(kwv & ((1u << bq) - 1u));
            }
            bool kf = (keepw[wq] >> bq) & 1u;
            int m = kf ? kb : (nk + (r - kb));
            int q = order[r];
            g_sel[base + m] = q;
            vk[base + m] = kf ? 1.0f : 0.0f;
            fl[base + m] = kf ? (float)label[q] : -1.0f;
            fs[base + m] = kf ? score[q] : 0.0f;
            float* pb = fb + (size_t)(base + m) * 4;
            pb[0] = kf ? bx1[q] : 0.0f;
            pb[1] = kf ? by1[q] : 0.0f;
            pb[2] = kf ? bx2[q] : 0.0f;
            pb[3] = kf ? by2[q] : 0.0f;
        }
    }

    // ------------------- last-block epilogue: keypoint gather ---------------
    __threadfence();
    __syncthreads();
    __shared__ int s_last;
    if (tid == 0) {
        int old = atomicAdd(&g_done, 1);
        s_last = (old == GRID_TOTAL - 1) ? 1 : 0;
    }
    __syncthreads();
    if (s_last) {
        float* ak = out + BN * 6;
        const float* vk = out + BN * 6 + BN * NK * 3;
        const float* fb = out + BN;
        for (int idx = tid; idx < NSLICES; idx += TB) {
            int k  = idx % NK;
            int bm = idx / NK;                 // b*NQ + m
            float* o = ak + (size_t)idx * 3;
            if (vk[bm] != 0.0f) {
                int b = bm / NQ;
                int q = g_sel[bm];
                const float* kp = g_kpts + ((size_t)(b * NQ + q) * NK + k) * 3;
                const float* pb = fb + (size_t)bm * 4;
                float x1 = pb[0], y1 = pb[1], x2 = pb[2], y2 = pb[3];
                o[0] = x1 + kp[0] * (x2 - x1);
                o[1] = y1 + kp[1] * (y2 - y1);
                o[2] = kp[2];
            } else {
                o[0] = 0.0f; o[1] = 0.0f; o[2] = 0.0f;
            }
        }
        if (tid == 0) g_done = 0;   // reset for next graph replay
    }
}

// ---------------------------------------------------------------------------
extern "C" void kernel_launch(void* const* d_in, const int* in_sizes, int n_in,
                              void* d_out, int out_size) {
    const float* logits = (const float*)d_in[0];   // (4,300,80)
    const float* boxes  = (const float*)d_in[1];   // (4,300,4)
    const float* hm     = (const float*)d_in[2];   // (4,300,17,64,64)
    const float* off    = (const float*)d_in[3];   // (4,300,17,2)
    const float* sizes  = (const float*)d_in[4];   // (4,2)
    float* out = (float*)d_out;

    fused_kernel<<<GRID_TOTAL, TB>>>(logits, boxes, sizes, hm, off, out);
}

// round 4
// speedup vs baseline: 2.8471x; 1.1449x over previous
#include <cuda_runtime.h>
#include <math.h>

#define BATCH 4
#define NQ    300
#define NC    80
#define NK    17
#define HW    4096
#define NWORDS 10                      // ceil(300/32)
#define BN    (BATCH*NQ)
#define TB    256
#define NSLICES (BATCH*NQ*NK)          // 20400
#define GRID_TOTAL (BATCH + NSLICES)   // 20404
#define EPI   32                       // epilogue blocks

#define NEGV (-1000000000.0f)
#define IOU_THR   0.7f
#define SCORE_THR 0.01f

// scratch
__device__ float g_kpts[NSLICES * 3];  // per (b,n,k): nx, ny, maxval
__device__ int   g_sel[BN];            // selected original query per slot
__device__ int   g_done  = 0;
__device__ int   g_done2 = 0;

// ---- shared buffer layout (single buffer so branches overlap, 8 blocks/SM) ----
#define OFF_MASK   0          // u32 [NQ][NWORDS]  = 12000 B
#define OFF_OBOX   12000      // float4[NQ]        = 4800
#define OFF_BX1    16800      // float[NQ]
#define OFF_BY1    18000
#define OFF_BX2    19200
#define OFF_BY2    20400
#define OFF_OAREA  21600
#define OFF_SCORE  22800
#define OFF_SKEY   24000      // 16B aligned
#define OFF_LABEL  25200      // int[NQ]
#define OFF_ORDER  26400      // int[NQ]
#define OFF_VALIDA 27600      // u8[NQ]
#define OFF_VS     27900      // u8[NQ]
#define OFF_RED    28208      // float[32] / keepw u32[10]
#define OFF_MISC   28336      // s_maxc
#define SBUF_SIZE  28352

__global__ void __launch_bounds__(TB)
fused_kernel(const float* __restrict__ logits,
             const float* __restrict__ boxes,
             const float* __restrict__ sizes,
             const float* __restrict__ hm,
             const float* __restrict__ off,
             float* __restrict__ out) {
    __shared__ __align__(16) unsigned char sbuf[SBUF_SIZE];
    __shared__ int s_rank;
    const int tid = threadIdx.x;

    if (blockIdx.x >= BATCH) {
        // ---------------- heatmap argmax: one block per slice ----------------
        float* swv = (float*)(sbuf);
        int*   swi = (int*)(sbuf + 64);
        const int slice = blockIdx.x - BATCH;
        const float4* p = reinterpret_cast<const float4*>(hm) + (size_t)slice * (HW / 4);

        // two independent accumulators (A: vi in {t, t+256}, B: {t+512, t+768};
        // all A element-indices < all B element-indices for a fixed thread)
        float bA = -INFINITY, bB = -INFINITY;
        int iA = 0, iB = 0;
        {
            float4 v0 = p[tid];
            float4 v1 = p[tid + 256];
            float4 v2 = p[tid + 512];
            float4 v3 = p[tid + 768];
            int b0 = tid * 4, b1 = (tid + 256) * 4, b2 = (tid + 512) * 4, b3 = (tid + 768) * 4;
            if (v0.x > bA) { bA = v0.x; iA = b0; }
            if (v0.y > bA) { bA = v0.y; iA = b0 + 1; }
            if (v0.z > bA) { bA = v0.z; iA = b0 + 2; }
            if (v0.w > bA) { bA = v0.w; iA = b0 + 3; }
            if (v1.x > bA) { bA = v1.x; iA = b1; }
            if (v1.y > bA) { bA = v1.y; iA = b1 + 1; }
            if (v1.z > bA) { bA = v1.z; iA = b1 + 2; }
            if (v1.w > bA) { bA = v1.w; iA = b1 + 3; }
            if (v2.x > bB) { bB = v2.x; iB = b2; }
            if (v2.y > bB) { bB = v2.y; iB = b2 + 1; }
            if (v2.z > bB) { bB = v2.z; iB = b2 + 2; }
            if (v2.w > bB) { bB = v2.w; iB = b2 + 3; }
            if (v3.x > bB) { bB = v3.x; iB = b3; }
            if (v3.y > bB) { bB = v3.y; iB = b3 + 1; }
            if (v3.z > bB) { bB = v3.z; iB = b3 + 2; }
            if (v3.w > bB) { bB = v3.w; iB = b3 + 3; }
        }
        float best = bA; int bi = iA;
        if (bB > best) { best = bB; bi = iB; }   // B indices always larger

#pragma unroll
        for (int o = 16; o > 0; o >>= 1) {
            float ov = __shfl_down_sync(0xFFFFFFFFu, best, o);
            int   oi = __shfl_down_sync(0xFFFFFFFFu, bi, o);
            if (ov > best || (ov == best && oi < bi)) { best = ov; bi = oi; }
        }
        if ((tid & 31) == 0) { swv[tid >> 5] = best; swi[tid >> 5] = bi; }
        __syncthreads();
        if (tid == 0) {
#pragma unroll
            for (int w = 1; w < 8; w++) {
                float ov = swv[w]; int oi = swi[w];
                if (ov > best || (ov == best && oi < bi)) { best = ov; bi = oi; }
            }
            float offx = off[(size_t)slice * 2 + 0];
            float offy = off[(size_t)slice * 2 + 1];
            float nx = (float)(bi & 63) / 63.0f + offx;
            float ny = (float)(bi >> 6) / 63.0f + offy;
            nx = fminf(fmaxf(nx, 0.0f), 1.0f);
            ny = fminf(fmaxf(ny, 0.0f), 1.0f);
            float* o = g_kpts + (size_t)slice * 3;
            o[0] = nx; o[1] = ny; o[2] = best;
        }
    } else {
        // ---------------- NMS core: one block per batch ----------------------
        const int b = blockIdx.x;
        unsigned int* mask = (unsigned int*)(sbuf + OFF_MASK);   // [NQ][NWORDS]
        float4* obox  = (float4*)(sbuf + OFF_OBOX);
        float* bx1    = (float*)(sbuf + OFF_BX1);
        float* by1    = (float*)(sbuf + OFF_BY1);
        float* bx2    = (float*)(sbuf + OFF_BX2);
        float* by2    = (float*)(sbuf + OFF_BY2);
        float* oarea  = (float*)(sbuf + OFF_OAREA);
        float* score  = (float*)(sbuf + OFF_SCORE);
        float* skey   = (float*)(sbuf + OFF_SKEY);
        int*   label  = (int*)(sbuf + OFF_LABEL);
        int*   order  = (int*)(sbuf + OFF_ORDER);
        unsigned char* validA = (unsigned char*)(sbuf + OFF_VALIDA);
        unsigned char* vs     = (unsigned char*)(sbuf + OFF_VS);
        float* red    = (float*)(sbuf + OFF_RED);
        unsigned int* keepw = (unsigned int*)(sbuf + OFF_RED);   // reused after red
        float* s_maxc = (float*)(sbuf + OFF_MISC);

        const float s0 = sizes[b * 2 + 0];
        const float s1 = sizes[b * 2 + 1];

        // --- abs boxes + score/label ---
        float lmax = 0.0f;
        for (int n = tid; n < NQ; n += TB) {
            const float* pb = boxes + ((size_t)b * NQ + n) * 4;
            float cx = pb[0], cy = pb[1], w = pb[2], h = pb[3];
            float x1 = (cx - w / 2.0f) * s0;
            float y1 = (cy - h / 2.0f) * s1;
            float x2 = (cx + w / 2.0f) * s0;
            float y2 = (cy + h / 2.0f) * s1;
            bx1[n] = x1; by1[n] = y1; bx2[n] = x2; by2[n] = y2;
            lmax = fmaxf(lmax, fmaxf(fmaxf(fabsf(x1), fabsf(y1)),
                                     fmaxf(fabsf(x2), fabsf(y2))));
            const float4* pl4 = reinterpret_cast<const float4*>(
                logits + ((size_t)b * NQ + n) * NC);
            float bestv = -INFINITY;
            int   bl = 0;
#pragma unroll 4
            for (int c4 = 0; c4 < NC / 4; c4++) {
                float4 v = pl4[c4];
                int c = c4 * 4;
                if (v.x > bestv) { bestv = v.x; bl = c; }
                if (v.y > bestv) { bestv = v.y; bl = c + 1; }
                if (v.z > bestv) { bestv = v.z; bl = c + 2; }
                if (v.w > bestv) { bestv = v.w; bl = c + 3; }
            }
            float sc = 1.0f / (1.0f + expf(-bestv));
            score[n]  = sc;
            label[n]  = bl;
            bool valid = sc > SCORE_THR;
            validA[n] = valid ? 1 : 0;
            skey[n]   = valid ? sc : NEGV;
        }
#pragma unroll
        for (int o = 16; o > 0; o >>= 1)
            lmax = fmaxf(lmax, __shfl_down_sync(0xFFFFFFFFu, lmax, o));
        if ((tid & 31) == 0) red[tid >> 5] = lmax;
        __syncthreads();
        if (tid == 0) {
            float m = red[0];
#pragma unroll
            for (int w = 1; w < 8; w++) m = fmaxf(m, red[w]);
            *s_maxc = m + 1.0f;
        }
        __syncthreads();
        const float maxc = *s_maxc;

        // --- stable descending rank sort (== jnp.argsort(-s)) ---
        for (int i = tid; i < NQ; i += TB) {
            float si = skey[i];
            int r = 0;
            const float4* sk4 = reinterpret_cast<const float4*>(skey);
#pragma unroll 5
            for (int j4 = 0; j4 < NQ / 4; j4++) {
                float4 v = sk4[j4];
                int j = j4 * 4;
                r += (v.x > si) || (v.x == si && (j    ) < i);
                r += (v.y > si) || (v.y == si && (j + 1) < i);
                r += (v.z > si) || (v.z == si && (j + 2) < i);
                r += (v.w > si) || (v.w == si && (j + 3) < i);
            }
            order[r] = i;
        }
        __syncthreads();

        // --- sorted class-offset boxes ---
        for (int r = tid; r < NQ; r += TB) {
            int i = order[r];
            float o = (float)label[i] * maxc;
            float x1 = bx1[i] + o, y1 = by1[i] + o;
            float x2 = bx2[i] + o, y2 = by2[i] + o;
            obox[r] = make_float4(x1, y1, x2, y2);
            oarea[r] = (x2 - x1) * (y2 - y1);
            vs[r] = validA[i];
        }
        __syncthreads();

        // --- IoU bitmask, w-major mapping: warp lanes share w -> broadcast LDS ---
        for (int u = tid; u < NQ * NWORDS; u += TB) {
            int i = u % NQ;
            int w = u / NQ;
            int j0 = w * 32;
            unsigned int bits = 0;
            if (j0 + 31 > i) {                     // some j in word can exceed i
                float4 bi4 = obox[i];
                float ai = oarea[i];
                int jend = (NQ - j0 < 32) ? (NQ - j0) : 32;
                for (int jj = 0; jj < jend; jj++) {
                    int j = j0 + jj;
                    if (j > i) {
                        float4 bj = obox[j];
                        float iw = fmaxf(fminf(bi4.z, bj.z) - fmaxf(bi4.x, bj.x), 0.0f);
                        float ih = fmaxf(fminf(bi4.w, bj.w) - fmaxf(bi4.y, bj.y), 0.0f);
                        float inter = iw * ih;
                        if (inter > 0.0f) {        // inter==0 -> iou==0 (exact)
                            float iou = inter / (ai + oarea[j] - inter + 1e-9f);
                            if (iou > IOU_THR) bits |= (1u << jj);
                        }
                    }
                }
            }
            mask[i * NWORDS + w] = bits;
        }
        __syncthreads();

        // --- greedy pass: warp 0, lane w owns suppression word w ---
        if (tid < 32) {
            const int lane = tid;
            unsigned int supp_w = 0, kw_w = 0;
            for (int i = 0; i < NQ; i++) {
                unsigned int sw = __shfl_sync(0xFFFFFFFFu, supp_w, i >> 5);
                unsigned int k = (unsigned int)vs[i] & (((sw >> (i & 31)) & 1u) ^ 1u);
                if (lane == (i >> 5)) kw_w |= k << (i & 31);
                unsigned int m = 0u - k;
                if (lane < NWORDS) supp_w |= mask[i * NWORDS + lane] & m;
            }
            if (lane < NWORDS) keepw[lane] = kw_w;
        }
        __syncthreads();

        // --- stable partition via popcount + write fl/fb/fs/vk, stash g_sel ---
        const int base = b * NQ;
        float* fl = out;
        float* fb = out + BN;
        float* fs = out + BN * 5;
        float* vk = out + BN * 6 + BN * NK * 3;

        for (int r = tid; r < NQ; r += TB) {
            int wq = r >> 5, bq = r & 31;
            int kb = 0, nk = 0;
#pragma unroll
            for (int w = 0; w < NWORDS; w++) {
                unsigned int kwv = keepw[w];
                nk += __popc(kwv);
                if (w < wq)  kb += __popc(kwv);
                if (w == wq) kb += __popc(kwv & ((1u << bq) - 1u));
            }
            bool kf = (keepw[wq] >> bq) & 1u;
            int m = kf ? kb : (nk + (r - kb));
            int q = order[r];
            g_sel[base + m] = q;
            vk[base + m] = kf ? 1.0f : 0.0f;
            fl[base + m] = kf ? (float)label[q] : -1.0f;
            fs[base + m] = kf ? score[q] : 0.0f;
            float* pb = fb + (size_t)(base + m) * 4;
            pb[0] = kf ? bx1[q] : 0.0f;
            pb[1] = kf ? by1[q] : 0.0f;
            pb[2] = kf ? bx2[q] : 0.0f;
            pb[3] = kf ? by2[q] : 0.0f;
        }
    }

    // ------------- distributed last-EPI-blocks epilogue: keypoint gather -----
    __threadfence();
    __syncthreads();
    if (tid == 0) s_rank = atomicAdd(&g_done, 1);
    __syncthreads();
    const int rank = s_rank;
    if (rank >= GRID_TOTAL - EPI) {
        if (tid == 0) {
            while (atomicAdd(&g_done, 0) < GRID_TOTAL) {}
        }
        __syncthreads();
        __threadfence();
        float* ak = out + BN * 6;
        const float* vk = out + BN * 6 + BN * NK * 3;
        const float* fb = out + BN;
        const int er = rank - (GRID_TOTAL - EPI);
        for (int idx = er * TB + tid; idx < NSLICES; idx += EPI * TB) {
            int k  = idx % NK;
            int bm = idx / NK;                 // b*NQ + m
            float* o = ak + (size_t)idx * 3;
            if (vk[bm] != 0.0f) {
                int bq = bm / NQ;
                int q = g_sel[bm];
                const float* kp = g_kpts + ((size_t)(bq * NQ + q) * NK + k) * 3;
                const float* pb = fb + (size_t)bm * 4;
                float x1 = pb[0], y1 = pb[1], x2 = pb[2], y2 = pb[3];
                o[0] = x1 + kp[0] * (x2 - x1);
                o[1] = y1 + kp[1] * (y2 - y1);
                o[2] = kp[2];
            } else {
                o[0] = 0.0f; o[1] = 0.0f; o[2] = 0.0f;
            }
        }
        __threadfence();
        __syncthreads();
        if (tid == 0) {
            int o2 = atomicAdd(&g_done2, 1);
            if (o2 == EPI - 1) { g_done = 0; g_done2 = 0; }   // reset for replay
        }
    }
}

// ---------------------------------------------------------------------------
extern "C" void kernel_launch(void* const* d_in, const int* in_sizes, int n_in,
                              void* d_out, int out_size) {
    const float* logits = (const float*)d_in[0];   // (4,300,80)
    const float* boxes  = (const float*)d_in[1];   // (4,300,4)
    const float* hm     = (const float*)d_in[2];   // (4,300,17,64,64)
    const float* off    = (const float*)d_in[3];   // (4,300,17,2)
    const float* sizes  = (const float*)d_in[4];   // (4,2)
    float* out = (float*)d_out;

    fused_kernel<<<GRID_TOTAL, TB>>>(logits, boxes, sizes, hm, off, out);
}

// round 5
// speedup vs baseline: 3.0383x; 1.0672x over previous
#include <cuda_runtime.h>
#include <math.h>

#define BATCH 4
#define NQ    300
#define NC    80
#define NK    17
#define HW    4096
#define NWORDS 10                      // ceil(300/32)
#define BN    (BATCH*NQ)
#define TB    256
#define NSLICES (BATCH*NQ*NK)          // 20400
#define ARGB  1176                     // persistent argmax blocks
#define GRID_TOTAL (BATCH + ARGB)      // 1180 = <1 wave at 8 blocks/SM
#define EPI   32                       // epilogue blocks

#define NEGV (-1000000000.0f)
#define IOU_THR   0.7f
#define SCORE_THR 0.01f

// scratch
__device__ float g_kpts[NSLICES * 3];  // per (b,n,k): nx, ny, maxval
__device__ int   g_sel[BN];            // selected original query per slot
__device__ int   g_done  = 0;
__device__ int   g_done2 = 0;

// ---- shared buffer layout (single buffer shared by both branches) ----
#define OFF_MASK   0          // u32 [NQ][NWORDS]  = 12000 B
#define OFF_OBOX   12000      // float4[NQ]        = 4800
#define OFF_BX1    16800      // float[NQ]
#define OFF_BY1    18000
#define OFF_BX2    19200
#define OFF_BY2    20400
#define OFF_OAREA  21600
#define OFF_SCORE  22800
#define OFF_SKEY   24000      // 16B aligned
#define OFF_LABEL  25200      // int[NQ]
#define OFF_ORDER  26400      // int[NQ]
#define OFF_VALIDA 27600      // u8[NQ]
#define OFF_VS     27900      // u8[NQ]
#define OFF_RED    28208      // float[32] / keepw u32[10]
#define OFF_MISC   28336      // s_maxc
#define SBUF_SIZE  28352

__global__ void __launch_bounds__(TB)
fused_kernel(const float* __restrict__ logits,
             const float* __restrict__ boxes,
             const float* __restrict__ sizes,
             const float* __restrict__ hm,
             const float* __restrict__ off,
             float* __restrict__ out) {
    __shared__ __align__(16) unsigned char sbuf[SBUF_SIZE];
    __shared__ int s_rank;
    const int tid = threadIdx.x;

    if (blockIdx.x >= BATCH) {
        // ------- persistent heatmap argmax: ~17 slices per block -------------
        float* swv = (float*)(sbuf);                 // [8] per-warp max
        unsigned int* swi = (unsigned int*)(sbuf + 64); // [8] per-warp best idx
        const int a = blockIdx.x - BATCH;
        const int lane = tid & 31;
        const int wid  = tid >> 5;

        for (int s = a; s < NSLICES; s += ARGB) {
            const float4* p = reinterpret_cast<const float4*>(hm) + (size_t)s * (HW / 4);
            // 4 independent LDG.128 (MLP=4), 512B/warp contiguous each
            float4 v0 = p[tid];
            float4 v1 = p[tid + 256];
            float4 v2 = p[tid + 512];
            float4 v3 = p[tid + 768];

            // fmax tree (fma pipe, short critical path)
            float m0 = fmaxf(fmaxf(v0.x, v0.y), fmaxf(v0.z, v0.w));
            float m1 = fmaxf(fmaxf(v1.x, v1.y), fmaxf(v1.z, v1.w));
            float m2 = fmaxf(fmaxf(v2.x, v2.y), fmaxf(v2.z, v2.w));
            float m3 = fmaxf(fmaxf(v3.x, v3.y), fmaxf(v3.z, v3.w));
            float m = fmaxf(fmaxf(m0, m1), fmaxf(m2, m3));
#pragma unroll
            for (int o = 16; o > 0; o >>= 1)
                m = fmaxf(m, __shfl_xor_sync(0xFFFFFFFFu, m, o));
            if (lane == 0) swv[wid] = m;
            __syncthreads();
            float M = fmaxf(fmaxf(fmaxf(swv[0], swv[1]), fmaxf(swv[2], swv[3])),
                            fmaxf(fmaxf(swv[4], swv[5]), fmaxf(swv[6], swv[7])));

            // lowest global index equal to M (descending scan => lowest wins)
            unsigned int bi = 0xFFFFFFFFu;
            const int b0 = tid * 4, b1 = (tid + 256) * 4,
                      b2 = (tid + 512) * 4, b3 = (tid + 768) * 4;
            if (v3.w == M) bi = b3 + 3;
            if (v3.z == M) bi = b3 + 2;
            if (v3.y == M) bi = b3 + 1;
            if (v3.x == M) bi = b3;
            if (v2.w == M) bi = b2 + 3;
            if (v2.z == M) bi = b2 + 2;
            if (v2.y == M) bi = b2 + 1;
            if (v2.x == M) bi = b2;
            if (v1.w == M) bi = b1 + 3;
            if (v1.z == M) bi = b1 + 2;
            if (v1.y == M) bi = b1 + 1;
            if (v1.x == M) bi = b1;
            if (v0.w == M) bi = b0 + 3;
            if (v0.z == M) bi = b0 + 2;
            if (v0.y == M) bi = b0 + 1;
            if (v0.x == M) bi = b0;
            bi = __reduce_min_sync(0xFFFFFFFFu, bi);
            if (lane == 0) swi[wid] = bi;
            __syncthreads();
            if (tid == 0) {
                unsigned int best = swi[0];
#pragma unroll
                for (int w = 1; w < 8; w++) best = min(best, swi[w]);
                float offx = off[(size_t)s * 2 + 0];
                float offy = off[(size_t)s * 2 + 1];
                float nx = (float)(best & 63) / 63.0f + offx;
                float ny = (float)(best >> 6) / 63.0f + offy;
                nx = fminf(fmaxf(nx, 0.0f), 1.0f);
                ny = fminf(fmaxf(ny, 0.0f), 1.0f);
                float* o = g_kpts + (size_t)s * 3;
                o[0] = nx; o[1] = ny; o[2] = M;
            }
        }
    } else {
        // ---------------- NMS core: one block per batch ----------------------
        const int b = blockIdx.x;
        unsigned int* mask = (unsigned int*)(sbuf + OFF_MASK);   // [NQ][NWORDS]
        float4* obox  = (float4*)(sbuf + OFF_OBOX);
        float* bx1    = (float*)(sbuf + OFF_BX1);
        float* by1    = (float*)(sbuf + OFF_BY1);
        float* bx2    = (float*)(sbuf + OFF_BX2);
        float* by2    = (float*)(sbuf + OFF_BY2);
        float* oarea  = (float*)(sbuf + OFF_OAREA);
        float* score  = (float*)(sbuf + OFF_SCORE);
        float* skey   = (float*)(sbuf + OFF_SKEY);
        int*   label  = (int*)(sbuf + OFF_LABEL);
        int*   order  = (int*)(sbuf + OFF_ORDER);
        unsigned char* validA = (unsigned char*)(sbuf + OFF_VALIDA);
        unsigned char* vs     = (unsigned char*)(sbuf + OFF_VS);
        float* red    = (float*)(sbuf + OFF_RED);
        unsigned int* keepw = (unsigned int*)(sbuf + OFF_RED);   // reused after red
        float* s_maxc = (float*)(sbuf + OFF_MISC);

        const float s0 = sizes[b * 2 + 0];
        const float s1 = sizes[b * 2 + 1];

        // --- abs boxes + score/label ---
        float lmax = 0.0f;
        for (int n = tid; n < NQ; n += TB) {
            const float* pb = boxes + ((size_t)b * NQ + n) * 4;
            float cx = pb[0], cy = pb[1], w = pb[2], h = pb[3];
            float x1 = (cx - w / 2.0f) * s0;
            float y1 = (cy - h / 2.0f) * s1;
            float x2 = (cx + w / 2.0f) * s0;
            float y2 = (cy + h / 2.0f) * s1;
            bx1[n] = x1; by1[n] = y1; bx2[n] = x2; by2[n] = y2;
            lmax = fmaxf(lmax, fmaxf(fmaxf(fabsf(x1), fabsf(y1)),
                                     fmaxf(fabsf(x2), fabsf(y2))));
            const float4* pl4 = reinterpret_cast<const float4*>(
                logits + ((size_t)b * NQ + n) * NC);
            float bestv = -INFINITY;
            int   bl = 0;
#pragma unroll 4
            for (int c4 = 0; c4 < NC / 4; c4++) {
                float4 v = pl4[c4];
                int c = c4 * 4;
                if (v.x > bestv) { bestv = v.x; bl = c; }
                if (v.y > bestv) { bestv = v.y; bl = c + 1; }
                if (v.z > bestv) { bestv = v.z; bl = c + 2; }
                if (v.w > bestv) { bestv = v.w; bl = c + 3; }
            }
            float sc = 1.0f / (1.0f + expf(-bestv));
            score[n]  = sc;
            label[n]  = bl;
            bool valid = sc > SCORE_THR;
            validA[n] = valid ? 1 : 0;
            skey[n]   = valid ? sc : NEGV;
        }
#pragma unroll
        for (int o = 16; o > 0; o >>= 1)
            lmax = fmaxf(lmax, __shfl_down_sync(0xFFFFFFFFu, lmax, o));
        if ((tid & 31) == 0) red[tid >> 5] = lmax;
        __syncthreads();
        if (tid == 0) {
            float m = red[0];
#pragma unroll
            for (int w = 1; w < 8; w++) m = fmaxf(m, red[w]);
            *s_maxc = m + 1.0f;
        }
        __syncthreads();
        const float maxc = *s_maxc;

        // --- stable descending rank sort (== jnp.argsort(-s)) ---
        for (int i = tid; i < NQ; i += TB) {
            float si = skey[i];
            int r = 0;
            const float4* sk4 = reinterpret_cast<const float4*>(skey);
#pragma unroll 5
            for (int j4 = 0; j4 < NQ / 4; j4++) {
                float4 v = sk4[j4];
                int j = j4 * 4;
                r += (v.x > si) || (v.x == si && (j    ) < i);
                r += (v.y > si) || (v.y == si && (j + 1) < i);
                r += (v.z > si) || (v.z == si && (j + 2) < i);
                r += (v.w > si) || (v.w == si && (j + 3) < i);
            }
            order[r] = i;
        }
        __syncthreads();

        // --- sorted class-offset boxes ---
        for (int r = tid; r < NQ; r += TB) {
            int i = order[r];
            float o = (float)label[i] * maxc;
            float x1 = bx1[i] + o, y1 = by1[i] + o;
            float x2 = bx2[i] + o, y2 = by2[i] + o;
            obox[r] = make_float4(x1, y1, x2, y2);
            oarea[r] = (x2 - x1) * (y2 - y1);
            vs[r] = validA[i];
        }
        __syncthreads();

        // --- IoU bitmask, w-major mapping: warp lanes share w -> broadcast LDS ---
        for (int u = tid; u < NQ * NWORDS; u += TB) {
            int i = u % NQ;
            int w = u / NQ;
            int j0 = w * 32;
            unsigned int bits = 0;
            if (j0 + 31 > i) {
                float4 bi4 = obox[i];
                float ai = oarea[i];
                int jend = (NQ - j0 < 32) ? (NQ - j0) : 32;
                for (int jj = 0; jj < jend; jj++) {
                    int j = j0 + jj;
                    if (j > i) {
                        float4 bj = obox[j];
                        float iw = fmaxf(fminf(bi4.z, bj.z) - fmaxf(bi4.x, bj.x), 0.0f);
                        float ih = fmaxf(fminf(bi4.w, bj.w) - fmaxf(bi4.y, bj.y), 0.0f);
                        float inter = iw * ih;
                        if (inter > 0.0f) {        // inter==0 -> iou==0 (exact)
                            float iou = inter / (ai + oarea[j] - inter + 1e-9f);
                            if (iou > IOU_THR) bits |= (1u << jj);
                        }
                    }
                }
            }
            mask[i * NWORDS + w] = bits;
        }
        __syncthreads();

        // --- greedy pass: warp 0, lane w owns suppression word w ---
        if (tid < 32) {
            const int lane = tid;
            unsigned int supp_w = 0, kw_w = 0;
            for (int i = 0; i < NQ; i++) {
                unsigned int sw = __shfl_sync(0xFFFFFFFFu, supp_w, i >> 5);
                unsigned int k = (unsigned int)vs[i] & (((sw >> (i & 31)) & 1u) ^ 1u);
                if (lane == (i >> 5)) kw_w |= k << (i & 31);
                unsigned int m = 0u - k;
                if (lane < NWORDS) supp_w |= mask[i * NWORDS + lane] & m;
            }
            if (lane < NWORDS) keepw[lane] = kw_w;
        }
        __syncthreads();

        // --- stable partition via popcount + write fl/fb/fs/vk, stash g_sel ---
        const int base = b * NQ;
        float* fl = out;
        float* fb = out + BN;
        float* fs = out + BN * 5;
        float* vk = out + BN * 6 + BN * NK * 3;

        for (int r = tid; r < NQ; r += TB) {
            int wq = r >> 5, bq = r & 31;
            int kb = 0, nk = 0;
#pragma unroll
            for (int w = 0; w < NWORDS; w++) {
                unsigned int kwv = keepw[w];
                nk += __popc(kwv);
                if (w < wq)  kb += __popc(kwv);
                if (w == wq) kb += __popc(kwv & ((1u << bq) - 1u));
            }
            bool kf = (keepw[wq] >> bq) & 1u;
            int m = kf ? kb : (nk + (r - kb));
            int q = order[r];
            g_sel[base + m] = q;
            vk[base + m] = kf ? 1.0f : 0.0f;
            fl[base + m] = kf ? (float)label[q] : -1.0f;
            fs[base + m] = kf ? score[q] : 0.0f;
            float* pb = fb + (size_t)(base + m) * 4;
            pb[0] = kf ? bx1[q] : 0.0f;
            pb[1] = kf ? by1[q] : 0.0f;
            pb[2] = kf ? bx2[q] : 0.0f;
            pb[3] = kf ? by2[q] : 0.0f;
        }
    }

    // ------------- distributed last-EPI-blocks epilogue: keypoint gather -----
    __threadfence();
    __syncthreads();
    if (tid == 0) s_rank = atomicAdd(&g_done, 1);
    __syncthreads();
    const int rank = s_rank;
    if (rank >= GRID_TOTAL - EPI) {
        if (tid == 0) {
            while (atomicAdd(&g_done, 0) < GRID_TOTAL) {}
        }
        __syncthreads();
        __threadfence();
        float* ak = out + BN * 6;
        const float* vk = out + BN * 6 + BN * NK * 3;
        const float* fb = out + BN;
        const int er = rank - (GRID_TOTAL - EPI);
        for (int idx = er * TB + tid; idx < NSLICES; idx += EPI * TB) {
            int k  = idx % NK;
            int bm = idx / NK;                 // b*NQ + m
            float* o = ak + (size_t)idx * 3;
            if (vk[bm] != 0.0f) {
                int bq = bm / NQ;
                int q = g_sel[bm];
                const float* kp = g_kpts + ((size_t)(bq * NQ + q) * NK + k) * 3;
                const float* pb = fb + (size_t)bm * 4;
                float x1 = pb[0], y1 = pb[1], x2 = pb[2], y2 = pb[3];
                o[0] = x1 + kp[0] * (x2 - x1);
                o[1] = y1 + kp[1] * (y2 - y1);
                o[2] = kp[2];
            } else {
                o[0] = 0.0f; o[1] = 0.0f; o[2] = 0.0f;
            }
        }
        __threadfence();
        __syncthreads();
        if (tid == 0) {
            int o2 = atomicAdd(&g_done2, 1);
            if (o2 == EPI - 1) { g_done = 0; g_done2 = 0; }   // reset for replay
        }
    }
}

// ---------------------------------------------------------------------------
extern "C" void kernel_launch(void* const* d_in, const int* in_sizes, int n_in,
                              void* d_out, int out_size) {
    const float* logits = (const float*)d_in[0];   // (4,300,80)
    const float* boxes  = (const float*)d_in[1];   // (4,300,4)
    const float* hm     = (const float*)d_in[2];   // (4,300,17,64,64)
    const float* off    = (const float*)d_in[3];   // (4,300,17,2)
    const float* sizes  = (const float*)d_in[4];   // (4,2)
    float* out = (float*)d_out;

    fused_kernel<<<GRID_TOTAL, TB>>>(logits, boxes, sizes, hm, off, out);
}